// round 6
// baseline (speedup 1.0000x reference)
#include <cuda_runtime.h>
#include <cuda_fp16.h>
#include <cstdint>

#define NT 4096
#define DI 1024

// ---- scratch (__device__ globals per allocation rules) ----
__device__ __half g_X[NT * DI];           // fp16 x
__device__ __half g_Q[NT * DI];           // fp16 Q
__device__ __half g_K[NT * DI];           // fp16 K
__device__ float  g_V[NT * DI];           // fp32 V (pre-transpose)
__device__ __half g_Vt[DI * NT];          // fp16 V^T
__device__ __half g_WT[3 * DI * DI];      // fp16 W^T
__device__ float  g_S[(size_t)NT * NT];   // fp32 scores
__device__ __half g_P[(size_t)NT * NT];   // fp16 probs (zero-padded tail)

// ============================ helpers ============================
__device__ __forceinline__ uint32_t smem_u32(const void* p) {
    uint32_t a;
    asm("{ .reg .u64 t; cvta.to.shared.u64 t, %1; cvt.u32.u64 %0, t; }" : "=r"(a) : "l"(p));
    return a;
}
__device__ __forceinline__ void cp16(uint32_t saddr, const void* g) {
    asm volatile("cp.async.cg.shared.global [%0], [%1], 16;" :: "r"(saddr), "l"(g));
}
__device__ __forceinline__ void cp_commit() { asm volatile("cp.async.commit_group;"); }
__device__ __forceinline__ void cp_wait2() { asm volatile("cp.async.wait_group 2;" ::: "memory"); }

__device__ __forceinline__ void mma_f16(float* c, const uint32_t* a, const uint32_t* b) {
    asm volatile(
        "mma.sync.aligned.m16n8k16.row.col.f32.f16.f16.f32 "
        "{%0,%1,%2,%3}, {%4,%5,%6,%7}, {%8,%9}, {%0,%1,%2,%3};"
        : "+f"(c[0]), "+f"(c[1]), "+f"(c[2]), "+f"(c[3])
        : "r"(a[0]), "r"(a[1]), "r"(a[2]), "r"(a[3]), "r"(b[0]), "r"(b[1]));
}
__device__ __forceinline__ void ldm_x4(uint32_t* r, uint32_t addr) {
    asm volatile("ldmatrix.sync.aligned.m8n8.x4.shared.b16 {%0,%1,%2,%3}, [%4];"
        : "=r"(r[0]), "=r"(r[1]), "=r"(r[2]), "=r"(r[3]) : "r"(addr));
}

// SMEM tile geometry: rows of 32 halves (64B); 2 rows per 128B line;
// 16B chunks XOR-swizzled within the line by (line & 7).
__device__ __forceinline__ uint32_t sw_chunk(int r, int q) {
    int line = r >> 1;
    int ch = (((r & 1) << 2) | q) ^ (line & 7);
    return (uint32_t)(line * 128 + ch * 16);
}

// ============================ GEMM ============================
#define BM 128
#define BK 32
#define A_BYTES (BM * 64)               // 8192

// Warp tile = 64 x (NI*8). CTA tile = 128 x (NI*32). 8 warps (2x4).
template <int NI, typename OutT>
__device__ __forceinline__ void gemm_tile(
    const __half* __restrict__ A, int lda,
    const __half* __restrict__ B, int ldb,
    int row0, int col0, int kLen,
    float scale, const float* __restrict__ bias,
    OutT* __restrict__ Out, int ldo)
{
    constexpr int BN = NI * 32;
    constexpr int STAGE_BYTES = A_BYTES + BN * 64;

    extern __shared__ char sm[];
    const uint32_t sb = smem_u32(sm);
    const int tid  = threadIdx.x;
    const int lane = tid & 31;
    const int warp = tid >> 5;
    const int wm = warp >> 2;       // 0..1
    const int wn = warp & 3;        // 0..3

    float acc[4][NI][4];
#pragma unroll
    for (int mi = 0; mi < 4; mi++)
#pragma unroll
        for (int ni = 0; ni < NI; ni++)
#pragma unroll
            for (int q = 0; q < 4; q++) acc[mi][ni][q] = 0.f;

    const int nStages = kLen / BK;

    auto load_stage = [&](int s) {
        const uint32_t base = sb + (uint32_t)((s % 3) * STAGE_BYTES);
        const int k0 = s * BK;
#pragma unroll
        for (int i = 0; i < 2; i++) {
            int idx = tid + i * 256;
            int r = idx >> 2, q = idx & 3;
            cp16(base + sw_chunk(r, q),
                 A + (size_t)(row0 + r) * lda + k0 + q * 8);
        }
#pragma unroll
        for (int i = 0; i < NI / 2; i++) {
            int idx = tid + i * 256;
            int r = idx >> 2, q = idx & 3;
            cp16(base + A_BYTES + sw_chunk(r, q),
                 B + (size_t)(col0 + r) * ldb + k0 + q * 8);
        }
        cp_commit();
    };

    load_stage(0);
    load_stage(1);
    load_stage(2);   // nStages >= 4 in all uses

    // per-lane ldmatrix row components (stage/k16-invariant)
    const int laneA_r = wm * 64 + (lane & 7) + ((lane >> 3) & 1) * 8;  // + mi*16
    const int laneA_q = lane >> 4;                                     // + k16*2
    const int laneB_r7 = lane & 7;
    const int laneB_sub = lane >> 3;        // 0..3: (ni-pair half, k-chunk)

    for (int s = 0; s < nStages; s++) {
        cp_wait2();
        __syncthreads();
        const uint32_t abase = sb + (uint32_t)((s % 3) * STAGE_BYTES);
        const uint32_t bbase = abase + A_BYTES;
#pragma unroll
        for (int k16 = 0; k16 < 2; k16++) {
            uint32_t af[4][4], bf[NI][2];
#pragma unroll
            for (int mi = 0; mi < 4; mi++)
                ldm_x4(af[mi], abase + sw_chunk(laneA_r + mi * 16, k16 * 2 + laneA_q));
#pragma unroll
            for (int p = 0; p < NI / 2; p++) {
                // tiles: (ni=2p,k16lo),(ni=2p,k16hi) from lanes 0-15? No:
                // sub 0: ni=2p chunk lo; sub 1: ni=2p chunk hi;
                // sub 2: ni=2p+1 chunk lo; sub 3: ni=2p+1 chunk hi
                const int nrow = wn * (NI * 8) + (p * 2 + (laneB_sub >> 1)) * 8 + laneB_r7;
                const int qb = k16 * 2 + (laneB_sub & 1);
                uint32_t t[4];
                ldm_x4(t, bbase + sw_chunk(nrow, qb));
                bf[p * 2][0] = t[0]; bf[p * 2][1] = t[1];
                bf[p * 2 + 1][0] = t[2]; bf[p * 2 + 1][1] = t[3];
            }
#pragma unroll
            for (int mi = 0; mi < 4; mi++)
#pragma unroll
                for (int ni = 0; ni < NI; ni++)
                    mma_f16(acc[mi][ni], af[mi], bf[ni]);
        }
        __syncthreads();
        if (s + 3 < nStages) load_stage(s + 3);
        else cp_commit();   // keep wait_group accounting constant
    }

    // epilogue
#pragma unroll
    for (int mi = 0; mi < 4; mi++) {
#pragma unroll
        for (int ni = 0; ni < NI; ni++) {
            const int row = row0 + wm * 64 + mi * 16 + (lane >> 2);
            const int col = col0 + wn * (NI * 8) + ni * 8 + 2 * (lane & 3);
            float v00 = acc[mi][ni][0] * scale, v01 = acc[mi][ni][1] * scale;
            float v10 = acc[mi][ni][2] * scale, v11 = acc[mi][ni][3] * scale;
            if (bias) {
                const float b0 = bias[col], b1 = bias[col + 1];
                v00 += b0; v01 += b1; v10 += b0; v11 += b1;
            }
            if (sizeof(OutT) == 2) {
                __half2* d0 = (__half2*)((__half*)Out + (size_t)row * ldo + col);
                __half2* d1 = (__half2*)((__half*)Out + (size_t)(row + 8) * ldo + col);
                *d0 = __floats2half2_rn(v00, v01);
                *d1 = __floats2half2_rn(v10, v11);
            } else {
                *(float2*)((float*)Out + (size_t)row * ldo + col)       = make_float2(v00, v01);
                *(float2*)((float*)Out + (size_t)(row + 8) * ldo + col) = make_float2(v10, v11);
            }
        }
    }
}

#define SMEM8 (3 * (A_BYTES + 256 * 64))   // 73728
#define SMEM4 (3 * (A_BYTES + 128 * 64))   // 49152

// ============================ kernels ============================
__global__ __launch_bounds__(256, 1) void projQK_k(
    const float* __restrict__ bq, const float* __restrict__ bk)
{
    const int z = blockIdx.z;
    gemm_tile<8, __half>(g_X, DI, g_WT + (size_t)z * DI * DI, DI,
                         blockIdx.y * BM, blockIdx.x * 256, DI, 1.0f,
                         z == 0 ? bq : bk, z == 0 ? g_Q : g_K, DI);
}

__global__ __launch_bounds__(256, 1) void projV_k(const float* __restrict__ bv)
{
    gemm_tile<8, float>(g_X, DI, g_WT + (size_t)2 * DI * DI, DI,
                        blockIdx.y * BM, blockIdx.x * 256, DI, 1.0f, bv, g_V, DI);
}

__global__ __launch_bounds__(256, 1) void score_k()
{
    // lower-tri 128x256 blocks: count(rt) = rt/2 + 1, total 272
    int b = blockIdx.x, rt = 0;
    while (b >= (rt >> 1) + 1) { b -= (rt >> 1) + 1; rt++; }
    gemm_tile<8, float>(g_Q, DI, g_K, DI, rt * BM, b * 256, DI, 0.03125f,
                        nullptr, g_S, NT);
}

__global__ __launch_bounds__(256) void av_k(float* __restrict__ out)
{
    const int rt = 31 - blockIdx.y;   // heavy rows first
    gemm_tile<4, float>(g_P, NT, g_Vt, NT, rt * BM, blockIdx.x * 128,
                        (rt + 1) * BM, 1.0f, nullptr, out, DI);
}

__global__ void cvt_x_k(const float* __restrict__ x)
{
    const int i = blockIdx.x * blockDim.x + threadIdx.x;   // float4 index
    float4 v = ((const float4*)x)[i];
    __half2* d = (__half2*)(g_X + i * 4);
    d[0] = __floats2half2_rn(v.x, v.y);
    d[1] = __floats2half2_rn(v.z, v.w);
}

__global__ void transW_k(const float* __restrict__ Wq, const float* __restrict__ Wk,
                         const float* __restrict__ Wv)
{
    const float* in = (blockIdx.z == 0) ? Wq : (blockIdx.z == 1) ? Wk : Wv;
    __half* out = g_WT + (size_t)blockIdx.z * DI * DI;
    __shared__ float t[32][33];
    const int c0 = blockIdx.x * 32, r0 = blockIdx.y * 32;
    const int tx = threadIdx.x, ty = threadIdx.y;
#pragma unroll
    for (int j = 0; j < 32; j += 8) t[ty + j][tx] = in[(size_t)(r0 + ty + j) * DI + c0 + tx];
    __syncthreads();
#pragma unroll
    for (int j = 0; j < 32; j += 8)
        out[(size_t)(c0 + ty + j) * DI + r0 + tx] = __float2half_rn(t[tx][ty + j]);
}

__global__ void transV_k()
{
    __shared__ float t[32][33];
    const int c0 = blockIdx.x * 32, r0 = blockIdx.y * 32;  // r over 4096, c over 1024
    const int tx = threadIdx.x, ty = threadIdx.y;
#pragma unroll
    for (int j = 0; j < 32; j += 8) t[ty + j][tx] = g_V[(size_t)(r0 + ty + j) * DI + c0 + tx];
    __syncthreads();
#pragma unroll
    for (int j = 0; j < 32; j += 8)
        g_Vt[(size_t)(c0 + ty + j) * NT + r0 + tx] = __float2half_rn(t[tx][ty + j]);
}

// causal row softmax: read fp32 S, write fp16 probs with zero tail
__global__ __launch_bounds__(256) void softmax_k()
{
    __shared__ float buf[NT];
    __shared__ float red[256];
    const int i = blockIdx.x;
    const int valid = i + 1;
    const int tid = threadIdx.x;
    const float* row = g_S + (size_t)i * NT;
    __half* prow = g_P + (size_t)i * NT;

    float m = -1e30f;
    for (int j = tid; j < valid; j += 256) {
        float v = row[j];
        buf[j] = v;
        m = fmaxf(m, v);
    }
    red[tid] = m; __syncthreads();
    for (int s = 128; s > 0; s >>= 1) { if (tid < s) red[tid] = fmaxf(red[tid], red[tid + s]); __syncthreads(); }
    m = red[0]; __syncthreads();

    float sum = 0.f;
    for (int j = tid; j < valid; j += 256) {
        float e = __expf(buf[j] - m);
        buf[j] = e;
        sum += e;
    }
    red[tid] = sum; __syncthreads();
    for (int s = 128; s > 0; s >>= 1) { if (tid < s) red[tid] += red[tid + s]; __syncthreads(); }
    const float inv = 1.0f / red[0];
    __syncthreads();

    for (int j = tid; j < valid; j += 256) prow[j] = __float2half_rn(buf[j] * inv);
    for (int j = valid + tid; j < NT; j += 256) prow[j] = __float2half_rn(0.f);
}

// ============================ launch ============================
extern "C" void kernel_launch(void* const* d_in, const int* in_sizes, int n_in,
                              void* d_out, int out_size)
{
    const float* x  = (const float*)d_in[0];
    const float* Wq = (const float*)d_in[1];
    const float* bq = (const float*)d_in[2];
    const float* Wk = (const float*)d_in[3];
    const float* bk = (const float*)d_in[4];
    const float* Wv = (const float*)d_in[5];
    const float* bv = (const float*)d_in[6];
    float* out = (float*)d_out;

    cudaFuncSetAttribute(projQK_k, cudaFuncAttributeMaxDynamicSharedMemorySize, SMEM8);
    cudaFuncSetAttribute(projV_k,  cudaFuncAttributeMaxDynamicSharedMemorySize, SMEM8);
    cudaFuncSetAttribute(score_k,  cudaFuncAttributeMaxDynamicSharedMemorySize, SMEM8);
    cudaFuncSetAttribute(av_k,     cudaFuncAttributeMaxDynamicSharedMemorySize, SMEM4);

    cvt_x_k<<<NT * DI / 4 / 256, 256>>>(x);
    transW_k<<<dim3(32, 32, 3), dim3(32, 8)>>>(Wq, Wk, Wv);
    projQK_k<<<dim3(4, 32, 2), 256, SMEM8>>>(bq, bk);
    projV_k<<<dim3(4, 32), 256, SMEM8>>>(bv);
    transV_k<<<dim3(32, 128), dim3(32, 8)>>>();
    score_k<<<272, 256, SMEM8>>>();
    softmax_k<<<NT, 256>>>();
    av_k<<<dim3(8, 32), 256, SMEM4>>>(out);
}

// round 7
// speedup vs baseline: 1.0623x; 1.0623x over previous
#include <cuda_runtime.h>
#include <cuda_fp16.h>
#include <cstdint>

#define NT 4096
#define DI 1024

// ---- scratch (__device__ globals per allocation rules) ----
__device__ __half g_X[NT * DI];           // fp16 x
__device__ __half g_Q[NT * DI];           // fp16 Q
__device__ __half g_K[NT * DI];           // fp16 K
__device__ float  g_V[NT * DI];           // fp32 V (pre-transpose)
__device__ __half g_Vt[DI * NT];          // fp16 V^T
__device__ __half g_WT[3 * DI * DI];      // fp16 W^T
__device__ float  g_S[(size_t)NT * NT];   // fp32 scores
__device__ __half g_P[(size_t)NT * NT];   // fp16 probs (zero-padded tail)

// ============================ helpers ============================
__device__ __forceinline__ uint32_t smem_u32(const void* p) {
    uint32_t a;
    asm("{ .reg .u64 t; cvta.to.shared.u64 t, %1; cvt.u32.u64 %0, t; }" : "=r"(a) : "l"(p));
    return a;
}
__device__ __forceinline__ void cp16(uint32_t saddr, const void* g) {
    asm volatile("cp.async.cg.shared.global [%0], [%1], 16;" :: "r"(saddr), "l"(g));
}
__device__ __forceinline__ void cp_commit() { asm volatile("cp.async.commit_group;"); }
__device__ __forceinline__ void cp_wait2() { asm volatile("cp.async.wait_group 2;" ::: "memory"); }

__device__ __forceinline__ void mma_f16(float* c, const uint32_t* a, const uint32_t* b) {
    asm volatile(
        "mma.sync.aligned.m16n8k16.row.col.f32.f16.f16.f32 "
        "{%0,%1,%2,%3}, {%4,%5,%6,%7}, {%8,%9}, {%0,%1,%2,%3};"
        : "+f"(c[0]), "+f"(c[1]), "+f"(c[2]), "+f"(c[3])
        : "r"(a[0]), "r"(a[1]), "r"(a[2]), "r"(a[3]), "r"(b[0]), "r"(b[1]));
}
__device__ __forceinline__ void ldm_x4(uint32_t* r, uint32_t addr) {
    asm volatile("ldmatrix.sync.aligned.m8n8.x4.shared.b16 {%0,%1,%2,%3}, [%4];"
        : "=r"(r[0]), "=r"(r[1]), "=r"(r[2]), "=r"(r[3]) : "r"(addr));
}

// SMEM tile geometry: rows of 32 halves (64B); 2 rows per 128B line;
// 16B chunks XOR-swizzled within the line by (line & 7).
__device__ __forceinline__ uint32_t sw_chunk(int r, int q) {
    int line = r >> 1;
    int ch = (((r & 1) << 2) | q) ^ (line & 7);
    return (uint32_t)(line * 128 + ch * 16);
}

// ============================ GEMM ============================
#define BM 128
#define BN 128
#define BK 32
#define A_BYTES (BM * 64)                 // 8192
#define STAGE_BYTES (A_BYTES + BN * 64)   // 16384
#define SMEM_T (3 * STAGE_BYTES)          // 49152

// CTA tile 128x128, 8 warps (2x4), warp tile 64x32 (NI=4). 2 CTAs/SM.
template <typename OutT>
__device__ __forceinline__ void gemm_tile(
    const __half* __restrict__ A, int lda,
    const __half* __restrict__ B, int ldb,
    int row0, int col0, int kLen,
    float scale, const float* __restrict__ bias,
    OutT* __restrict__ Out, int ldo)
{
    constexpr int NI = 4;

    extern __shared__ char sm[];
    const uint32_t sb = smem_u32(sm);
    const int tid  = threadIdx.x;
    const int lane = tid & 31;
    const int warp = tid >> 5;
    const int wm = warp >> 2;       // 0..1
    const int wn = warp & 3;        // 0..3

    float acc[4][NI][4];
#pragma unroll
    for (int mi = 0; mi < 4; mi++)
#pragma unroll
        for (int ni = 0; ni < NI; ni++)
#pragma unroll
            for (int q = 0; q < 4; q++) acc[mi][ni][q] = 0.f;

    const int nStages = kLen / BK;

    auto load_stage = [&](int s) {
        const uint32_t base = sb + (uint32_t)((s % 3) * STAGE_BYTES);
        const int k0 = s * BK;
#pragma unroll
        for (int i = 0; i < 2; i++) {
            int idx = tid + i * 256;
            int r = idx >> 2, q = idx & 3;
            cp16(base + sw_chunk(r, q),
                 A + (size_t)(row0 + r) * lda + k0 + q * 8);
        }
#pragma unroll
        for (int i = 0; i < 2; i++) {
            int idx = tid + i * 256;
            int r = idx >> 2, q = idx & 3;
            cp16(base + A_BYTES + sw_chunk(r, q),
                 B + (size_t)(col0 + r) * ldb + k0 + q * 8);
        }
        cp_commit();
    };

    load_stage(0);
    load_stage(1);
    load_stage(2);   // nStages >= 4 in all uses

    // per-lane ldmatrix row components (stage/k16-invariant)
    const int laneA_r = wm * 64 + (lane & 7) + ((lane >> 3) & 1) * 8;  // + mi*16
    const int laneA_q = lane >> 4;                                     // + k16*2
    const int laneB_r7 = lane & 7;
    const int laneB_sub = lane >> 3;        // 0..3

    for (int s = 0; s < nStages; s++) {
        cp_wait2();
        __syncthreads();
        const uint32_t abase = sb + (uint32_t)((s % 3) * STAGE_BYTES);
        const uint32_t bbase = abase + A_BYTES;
#pragma unroll
        for (int k16 = 0; k16 < 2; k16++) {
            uint32_t af[4][4], bf[NI][2];
#pragma unroll
            for (int mi = 0; mi < 4; mi++)
                ldm_x4(af[mi], abase + sw_chunk(laneA_r + mi * 16, k16 * 2 + laneA_q));
#pragma unroll
            for (int p = 0; p < NI / 2; p++) {
                // sub 0: ni=2p lo-chunk; 1: ni=2p hi; 2: ni=2p+1 lo; 3: ni=2p+1 hi
                const int nrow = wn * (NI * 8) + (p * 2 + (laneB_sub >> 1)) * 8 + laneB_r7;
                const int qb = k16 * 2 + (laneB_sub & 1);
                uint32_t t[4];
                ldm_x4(t, bbase + sw_chunk(nrow, qb));
                bf[p * 2][0] = t[0]; bf[p * 2][1] = t[1];
                bf[p * 2 + 1][0] = t[2]; bf[p * 2 + 1][1] = t[3];
            }
#pragma unroll
            for (int mi = 0; mi < 4; mi++)
#pragma unroll
                for (int ni = 0; ni < NI; ni++)
                    mma_f16(acc[mi][ni], af[mi], bf[ni]);
        }
        __syncthreads();
        if (s + 3 < nStages) load_stage(s + 3);
        else cp_commit();   // keep wait_group accounting constant
    }

    // epilogue
#pragma unroll
    for (int mi = 0; mi < 4; mi++) {
#pragma unroll
        for (int ni = 0; ni < NI; ni++) {
            const int row = row0 + wm * 64 + mi * 16 + (lane >> 2);
            const int col = col0 + wn * (NI * 8) + ni * 8 + 2 * (lane & 3);
            float v00 = acc[mi][ni][0] * scale, v01 = acc[mi][ni][1] * scale;
            float v10 = acc[mi][ni][2] * scale, v11 = acc[mi][ni][3] * scale;
            if (bias) {
                const float b0 = bias[col], b1 = bias[col + 1];
                v00 += b0; v01 += b1; v10 += b0; v11 += b1;
            }
            if (sizeof(OutT) == 2) {
                __half2* d0 = (__half2*)((__half*)Out + (size_t)row * ldo + col);
                __half2* d1 = (__half2*)((__half*)Out + (size_t)(row + 8) * ldo + col);
                *d0 = __floats2half2_rn(v00, v01);
                *d1 = __floats2half2_rn(v10, v11);
            } else {
                *(float2*)((float*)Out + (size_t)row * ldo + col)       = make_float2(v00, v01);
                *(float2*)((float*)Out + (size_t)(row + 8) * ldo + col) = make_float2(v10, v11);
            }
        }
    }
}

// ============================ kernels ============================
__global__ __launch_bounds__(256, 2) void projQK_k(
    const float* __restrict__ bq, const float* __restrict__ bk)
{
    const int z = blockIdx.z;
    gemm_tile<__half>(g_X, DI, g_WT + (size_t)z * DI * DI, DI,
                      blockIdx.y * BM, blockIdx.x * BN, DI, 1.0f,
                      z == 0 ? bq : bk, z == 0 ? g_Q : g_K, DI);
}

__global__ __launch_bounds__(256, 2) void projV_k(const float* __restrict__ bv)
{
    gemm_tile<float>(g_X, DI, g_WT + (size_t)2 * DI * DI, DI,
                     blockIdx.y * BM, blockIdx.x * BN, DI, 1.0f, bv, g_V, DI);
}

__global__ __launch_bounds__(256, 2) void score_k()
{
    // lower-tri 128x128 blocks: count(rt) = rt+1, total 528
    int b = blockIdx.x, rt = 0;
    while (b > rt) { b -= rt + 1; rt++; }
    gemm_tile<float>(g_Q, DI, g_K, DI, rt * BM, b * BN, DI, 0.03125f,
                     nullptr, g_S, NT);
}

__global__ __launch_bounds__(256, 2) void av_k(float* __restrict__ out)
{
    const int rt = 31 - blockIdx.y;   // heavy rows first
    gemm_tile<float>(g_P, NT, g_Vt, NT, rt * BM, blockIdx.x * BN,
                     (rt + 1) * BM, 1.0f, nullptr, out, DI);
}

__global__ void cvt_x_k(const float* __restrict__ x)
{
    const int i = blockIdx.x * blockDim.x + threadIdx.x;   // float4 index
    float4 v = ((const float4*)x)[i];
    __half2* d = (__half2*)(g_X + i * 4);
    d[0] = __floats2half2_rn(v.x, v.y);
    d[1] = __floats2half2_rn(v.z, v.w);
}

__global__ void transW_k(const float* __restrict__ Wq, const float* __restrict__ Wk,
                         const float* __restrict__ Wv)
{
    const float* in = (blockIdx.z == 0) ? Wq : (blockIdx.z == 1) ? Wk : Wv;
    __half* out = g_WT + (size_t)blockIdx.z * DI * DI;
    __shared__ float t[32][33];
    const int c0 = blockIdx.x * 32, r0 = blockIdx.y * 32;
    const int tx = threadIdx.x, ty = threadIdx.y;
#pragma unroll
    for (int j = 0; j < 32; j += 8) t[ty + j][tx] = in[(size_t)(r0 + ty + j) * DI + c0 + tx];
    __syncthreads();
#pragma unroll
    for (int j = 0; j < 32; j += 8)
        out[(size_t)(c0 + ty + j) * DI + r0 + tx] = __float2half_rn(t[tx][ty + j]);
}

__global__ void transV_k()
{
    __shared__ float t[32][33];
    const int c0 = blockIdx.x * 32, r0 = blockIdx.y * 32;  // r over 4096, c over 1024
    const int tx = threadIdx.x, ty = threadIdx.y;
#pragma unroll
    for (int j = 0; j < 32; j += 8) t[ty + j][tx] = g_V[(size_t)(r0 + ty + j) * DI + c0 + tx];
    __syncthreads();
#pragma unroll
    for (int j = 0; j < 32; j += 8)
        g_Vt[(size_t)(c0 + ty + j) * NT + r0 + tx] = __float2half_rn(t[tx][ty + j]);
}

// causal row softmax: read fp32 S, write fp16 probs with zero tail
__global__ __launch_bounds__(256) void softmax_k()
{
    __shared__ float buf[NT];
    __shared__ float red[256];
    const int i = blockIdx.x;
    const int valid = i + 1;
    const int tid = threadIdx.x;
    const float* row = g_S + (size_t)i * NT;
    __half* prow = g_P + (size_t)i * NT;

    float m = -1e30f;
    for (int j = tid; j < valid; j += 256) {
        float v = row[j];
        buf[j] = v;
        m = fmaxf(m, v);
    }
    red[tid] = m; __syncthreads();
    for (int s = 128; s > 0; s >>= 1) { if (tid < s) red[tid] = fmaxf(red[tid], red[tid + s]); __syncthreads(); }
    m = red[0]; __syncthreads();

    float sum = 0.f;
    for (int j = tid; j < valid; j += 256) {
        float e = __expf(buf[j] - m);
        buf[j] = e;
        sum += e;
    }
    red[tid] = sum; __syncthreads();
    for (int s = 128; s > 0; s >>= 1) { if (tid < s) red[tid] += red[tid + s]; __syncthreads(); }
    const float inv = 1.0f / red[0];
    __syncthreads();

    for (int j = tid; j < valid; j += 256) prow[j] = __float2half_rn(buf[j] * inv);
    for (int j = valid + tid; j < NT; j += 256) prow[j] = __float2half_rn(0.f);
}

// ============================ launch ============================
extern "C" void kernel_launch(void* const* d_in, const int* in_sizes, int n_in,
                              void* d_out, int out_size)
{
    const float* x  = (const float*)d_in[0];
    const float* Wq = (const float*)d_in[1];
    const float* bq = (const float*)d_in[2];
    const float* Wk = (const float*)d_in[3];
    const float* bk = (const float*)d_in[4];
    const float* Wv = (const float*)d_in[5];
    const float* bv = (const float*)d_in[6];
    float* out = (float*)d_out;

    cudaFuncSetAttribute(projQK_k, cudaFuncAttributeMaxDynamicSharedMemorySize, SMEM_T);
    cudaFuncSetAttribute(projV_k,  cudaFuncAttributeMaxDynamicSharedMemorySize, SMEM_T);
    cudaFuncSetAttribute(score_k,  cudaFuncAttributeMaxDynamicSharedMemorySize, SMEM_T);
    cudaFuncSetAttribute(av_k,     cudaFuncAttributeMaxDynamicSharedMemorySize, SMEM_T);

    cvt_x_k<<<NT * DI / 4 / 256, 256>>>(x);
    transW_k<<<dim3(32, 32, 3), dim3(32, 8)>>>(Wq, Wk, Wv);
    projQK_k<<<dim3(8, 32, 2), 256, SMEM_T>>>(bq, bk);
    projV_k<<<dim3(8, 32), 256, SMEM_T>>>(bv);
    transV_k<<<dim3(32, 128), dim3(32, 8)>>>();
    score_k<<<528, 256, SMEM_T>>>();
    softmax_k<<<NT, 256>>>();
    av_k<<<dim3(8, 32), 256, SMEM_T>>>(out);
}

// round 8
// speedup vs baseline: 1.1413x; 1.0744x over previous
#include <cuda_runtime.h>
#include <cuda_fp16.h>
#include <cstdint>

#define NT 4096
#define DI 1024

// ---- scratch (__device__ globals per allocation rules) ----
__device__ __half g_X[NT * DI];           // fp16 x
__device__ __half g_Q[NT * DI];           // fp16 Q
__device__ __half g_K[NT * DI];           // fp16 K
__device__ __half g_Vt[DI * NT];          // fp16 V^T (written directly by proj epilogue)
__device__ __half g_WT[3 * DI * DI];      // fp16 W^T
__device__ float  g_S[(size_t)NT * NT];   // fp32 scores
__device__ __half g_P[(size_t)NT * NT];   // fp16 probs (zero-padded tail)
__device__ float  g_Opart[3 * (size_t)NT * DI];  // split-K partials for av

// ============================ helpers ============================
__device__ __forceinline__ uint32_t smem_u32(const void* p) {
    uint32_t a;
    asm("{ .reg .u64 t; cvta.to.shared.u64 t, %1; cvt.u32.u64 %0, t; }" : "=r"(a) : "l"(p));
    return a;
}
__device__ __forceinline__ void cp16(uint32_t saddr, const void* g) {
    asm volatile("cp.async.cg.shared.global [%0], [%1], 16;" :: "r"(saddr), "l"(g));
}
__device__ __forceinline__ void cp_commit() { asm volatile("cp.async.commit_group;"); }
__device__ __forceinline__ void cp_wait2() { asm volatile("cp.async.wait_group 2;" ::: "memory"); }

__device__ __forceinline__ void mma_f16(float* c, const uint32_t* a, const uint32_t* b) {
    asm volatile(
        "mma.sync.aligned.m16n8k16.row.col.f32.f16.f16.f32 "
        "{%0,%1,%2,%3}, {%4,%5,%6,%7}, {%8,%9}, {%0,%1,%2,%3};"
        : "+f"(c[0]), "+f"(c[1]), "+f"(c[2]), "+f"(c[3])
        : "r"(a[0]), "r"(a[1]), "r"(a[2]), "r"(a[3]), "r"(b[0]), "r"(b[1]));
}
__device__ __forceinline__ void ldm_x4(uint32_t* r, uint32_t addr) {
    asm volatile("ldmatrix.sync.aligned.m8n8.x4.shared.b16 {%0,%1,%2,%3}, [%4];"
        : "=r"(r[0]), "=r"(r[1]), "=r"(r[2]), "=r"(r[3]) : "r"(addr));
}

// SMEM tile: rows of 32 halves (64B); 2 rows per 128B line; 16B chunks XOR-swizzled.
__device__ __forceinline__ uint32_t sw_chunk(int r, int q) {
    int line = r >> 1;
    int ch = (((r & 1) << 2) | q) ^ (line & 7);
    return (uint32_t)(line * 128 + ch * 16);
}

// ============================ GEMM ============================
#define BM 128
#define BN 128
#define BK 32
#define A_BYTES (BM * 64)                 // 8192
#define STAGE_BYTES (A_BYTES + BN * 64)   // 16384
#define SMEM_T (3 * STAGE_BYTES)          // 49152

// MODE: 0 = fp32 row-major out, 1 = fp16 row-major out, 2 = fp16 transposed out (V^T)
template <int MODE>
__device__ __forceinline__ void gemm_tile(
    const __half* __restrict__ A, int lda,
    const __half* __restrict__ B, int ldb,
    int row0, int col0, int kLen,
    float scale, const float* __restrict__ bias,
    void* __restrict__ Out, int ldo)
{
    constexpr int NI = 4;

    extern __shared__ char sm[];
    const uint32_t sb = smem_u32(sm);
    const int tid  = threadIdx.x;
    const int lane = tid & 31;
    const int warp = tid >> 5;
    const int wm = warp >> 2;       // 0..1
    const int wn = warp & 3;        // 0..3

    float acc[4][NI][4];
#pragma unroll
    for (int mi = 0; mi < 4; mi++)
#pragma unroll
        for (int ni = 0; ni < NI; ni++)
#pragma unroll
            for (int q = 0; q < 4; q++) acc[mi][ni][q] = 0.f;

    const int nStages = kLen / BK;   // >= 4 in all uses

    auto load_stage = [&](int s) {
        const uint32_t base = sb + (uint32_t)((s % 3) * STAGE_BYTES);
        const int k0 = s * BK;
#pragma unroll
        for (int i = 0; i < 2; i++) {
            int idx = tid + i * 256;
            int r = idx >> 2, q = idx & 3;
            cp16(base + sw_chunk(r, q),
                 A + (size_t)(row0 + r) * lda + k0 + q * 8);
        }
#pragma unroll
        for (int i = 0; i < 2; i++) {
            int idx = tid + i * 256;
            int r = idx >> 2, q = idx & 3;
            cp16(base + A_BYTES + sw_chunk(r, q),
                 B + (size_t)(col0 + r) * ldb + k0 + q * 8);
        }
        cp_commit();
    };

    load_stage(0);
    load_stage(1);
    load_stage(2);

    // per-lane ldmatrix row components (stage/k16-invariant)
    const int laneA_r = wm * 64 + (lane & 7) + ((lane >> 3) & 1) * 8;  // + mi*16
    const int laneA_q = lane >> 4;                                     // + k16*2
    const int laneB_r7 = lane & 7;
    const int laneB_sub = lane >> 3;        // 0..3

    for (int s = 0; s < nStages; s++) {
        cp_wait2();
        __syncthreads();
        const uint32_t abase = sb + (uint32_t)((s % 3) * STAGE_BYTES);
        const uint32_t bbase = abase + A_BYTES;
#pragma unroll
        for (int k16 = 0; k16 < 2; k16++) {
            uint32_t af[4][4], bf[NI][2];
#pragma unroll
            for (int mi = 0; mi < 4; mi++)
                ldm_x4(af[mi], abase + sw_chunk(laneA_r + mi * 16, k16 * 2 + laneA_q));
#pragma unroll
            for (int p = 0; p < NI / 2; p++) {
                const int nrow = wn * (NI * 8) + (p * 2 + (laneB_sub >> 1)) * 8 + laneB_r7;
                const int qb = k16 * 2 + (laneB_sub & 1);
                uint32_t t[4];
                ldm_x4(t, bbase + sw_chunk(nrow, qb));
                bf[p * 2][0] = t[0]; bf[p * 2][1] = t[1];
                bf[p * 2 + 1][0] = t[2]; bf[p * 2 + 1][1] = t[3];
            }
#pragma unroll
            for (int mi = 0; mi < 4; mi++)
#pragma unroll
                for (int ni = 0; ni < NI; ni++)
                    mma_f16(acc[mi][ni], af[mi], bf[ni]);
        }
        __syncthreads();
        if (s + 3 < nStages) load_stage(s + 3);
        else cp_commit();
    }

    // epilogue
#pragma unroll
    for (int mi = 0; mi < 4; mi++) {
#pragma unroll
        for (int ni = 0; ni < NI; ni++) {
            const int row = row0 + wm * 64 + mi * 16 + (lane >> 2);
            const int col = col0 + wn * (NI * 8) + ni * 8 + 2 * (lane & 3);
            float v00 = acc[mi][ni][0] * scale, v01 = acc[mi][ni][1] * scale;
            float v10 = acc[mi][ni][2] * scale, v11 = acc[mi][ni][3] * scale;
            if (bias) {
                const float b0 = bias[col], b1 = bias[col + 1];
                v00 += b0; v01 += b1; v10 += b0; v11 += b1;
            }
            if (MODE == 0) {
                *(float2*)((float*)Out + (size_t)row * ldo + col)       = make_float2(v00, v01);
                *(float2*)((float*)Out + (size_t)(row + 8) * ldo + col) = make_float2(v10, v11);
            } else if (MODE == 1) {
                *(__half2*)((__half*)Out + (size_t)row * ldo + col)       = __floats2half2_rn(v00, v01);
                *(__half2*)((__half*)Out + (size_t)(row + 8) * ldo + col) = __floats2half2_rn(v10, v11);
            } else {
                // transposed fp16: Out[col][row] with leading dim ldo
                __half* o = (__half*)Out;
                o[(size_t)col * ldo + row]           = __float2half_rn(v00);
                o[(size_t)(col + 1) * ldo + row]     = __float2half_rn(v01);
                o[(size_t)col * ldo + row + 8]       = __float2half_rn(v10);
                o[(size_t)(col + 1) * ldo + row + 8] = __float2half_rn(v11);
            }
        }
    }
}

// ============================ kernels ============================
// one launch for all three projections; z=2 writes V^T directly
__global__ __launch_bounds__(256, 2) void proj_k(
    const float* __restrict__ bq, const float* __restrict__ bk, const float* __restrict__ bv)
{
    const int z = blockIdx.z;
    const __half* W = g_WT + (size_t)z * DI * DI;
    const int r0 = blockIdx.y * BM, c0 = blockIdx.x * BN;
    if (z == 0)
        gemm_tile<1>(g_X, DI, W, DI, r0, c0, DI, 1.0f, bq, g_Q, DI);
    else if (z == 1)
        gemm_tile<1>(g_X, DI, W, DI, r0, c0, DI, 1.0f, bk, g_K, DI);
    else
        gemm_tile<2>(g_X, DI, W, DI, r0, c0, DI, 1.0f, bv, g_Vt, NT);
}

__global__ __launch_bounds__(256, 2) void score_k()
{
    // lower-tri 128x128 blocks: count(rt) = rt+1, total 528
    int b = blockIdx.x, rt = 0;
    while (b > rt) { b -= rt + 1; rt++; }
    gemm_tile<0>(g_Q, DI, g_K, DI, rt * BM, b * BN, DI, 0.03125f,
                 nullptr, g_S, NT);
}

// split-K av: chunks of <=1024 K. blockIdx.y in [0,80) -> (rt, kc).
__global__ __launch_bounds__(256, 2) void av_k(float* __restrict__ out)
{
    int y = blockIdx.y, rt = 0;
    while (y >= ((rt >> 3) + 1)) { y -= (rt >> 3) + 1; rt++; }
    const int kc = y;
    const int kStart = kc << 10;
    const int kEndFull = (rt + 1) << 7;
    const int kLen = min(kEndFull, kStart + 1024) - kStart;

    float* dst = (kc == 0) ? out : (g_Opart + (size_t)(kc - 1) * NT * DI);
    gemm_tile<0>(g_P + kStart, NT, g_Vt + kStart, NT,
                 rt * BM, blockIdx.x * BN, kLen, 1.0f, nullptr, dst, DI);
}

// fold split-K partials into out (rows with rt>=8 only), fixed order
__global__ __launch_bounds__(256) void reduce_k(float* __restrict__ out)
{
    const int row = 1024 + blockIdx.x;
    const int tid = threadIdx.x;
    const int nextra = (row >> 7) >> 3;   // 1..3
    float4* o4 = (float4*)(out + (size_t)row * DI) + tid;
    float4 v = *o4;
    for (int j = 0; j < nextra; j++) {
        const float4 p = *((const float4*)(g_Opart + (size_t)j * NT * DI + (size_t)row * DI) + tid);
        v.x += p.x; v.y += p.y; v.z += p.z; v.w += p.w;
    }
    *o4 = v;
}

__global__ void cvt_x_k(const float* __restrict__ x)
{
    const int i = blockIdx.x * blockDim.x + threadIdx.x;   // float4 index
    float4 v = ((const float4*)x)[i];
    __half2* d = (__half2*)(g_X + i * 4);
    d[0] = __floats2half2_rn(v.x, v.y);
    d[1] = __floats2half2_rn(v.z, v.w);
}

__global__ void transW_k(const float* __restrict__ Wq, const float* __restrict__ Wk,
                         const float* __restrict__ Wv)
{
    const float* in = (blockIdx.z == 0) ? Wq : (blockIdx.z == 1) ? Wk : Wv;
    __half* out = g_WT + (size_t)blockIdx.z * DI * DI;
    __shared__ float t[32][33];
    const int c0 = blockIdx.x * 32, r0 = blockIdx.y * 32;
    const int tx = threadIdx.x, ty = threadIdx.y;
#pragma unroll
    for (int j = 0; j < 32; j += 8) t[ty + j][tx] = in[(size_t)(r0 + ty + j) * DI + c0 + tx];
    __syncthreads();
#pragma unroll
    for (int j = 0; j < 32; j += 8)
        out[(size_t)(c0 + ty + j) * DI + r0 + tx] = __float2half_rn(t[tx][ty + j]);
}

// causal row softmax: read fp32 S, write fp16 probs with zero tail
__global__ __launch_bounds__(256) void softmax_k()
{
    __shared__ float buf[NT];
    __shared__ float red[256];
    const int i = blockIdx.x;
    const int valid = i + 1;
    const int tid = threadIdx.x;
    const float* row = g_S + (size_t)i * NT;
    __half* prow = g_P + (size_t)i * NT;

    float m = -1e30f;
    for (int j = tid; j < valid; j += 256) {
        float v = row[j];
        buf[j] = v;
        m = fmaxf(m, v);
    }
    red[tid] = m; __syncthreads();
    for (int s = 128; s > 0; s >>= 1) { if (tid < s) red[tid] = fmaxf(red[tid], red[tid + s]); __syncthreads(); }
    m = red[0]; __syncthreads();

    float sum = 0.f;
    for (int j = tid; j < valid; j += 256) {
        float e = __expf(buf[j] - m);
        buf[j] = e;
        sum += e;
    }
    red[tid] = sum; __syncthreads();
    for (int s = 128; s > 0; s >>= 1) { if (tid < s) red[tid] += red[tid + s]; __syncthreads(); }
    const float inv = 1.0f / red[0];
    __syncthreads();

    for (int j = tid; j < valid; j += 256) prow[j] = __float2half_rn(buf[j] * inv);
    for (int j = valid + tid; j < NT; j += 256) prow[j] = __float2half_rn(0.f);
}

// ============================ launch ============================
extern "C" void kernel_launch(void* const* d_in, const int* in_sizes, int n_in,
                              void* d_out, int out_size)
{
    const float* x  = (const float*)d_in[0];
    const float* Wq = (const float*)d_in[1];
    const float* bq = (const float*)d_in[2];
    const float* Wk = (const float*)d_in[3];
    const float* bk = (const float*)d_in[4];
    const float* Wv = (const float*)d_in[5];
    const float* bv = (const float*)d_in[6];
    float* out = (float*)d_out;

    cudaFuncSetAttribute(proj_k,  cudaFuncAttributeMaxDynamicSharedMemorySize, SMEM_T);
    cudaFuncSetAttribute(score_k, cudaFuncAttributeMaxDynamicSharedMemorySize, SMEM_T);
    cudaFuncSetAttribute(av_k,    cudaFuncAttributeMaxDynamicSharedMemorySize, SMEM_T);

    cvt_x_k<<<NT * DI / 4 / 256, 256>>>(x);
    transW_k<<<dim3(32, 32, 3), dim3(32, 8)>>>(Wq, Wk, Wv);
    proj_k<<<dim3(8, 32, 3), 256, SMEM_T>>>(bq, bk, bv);
    score_k<<<528, 256, SMEM_T>>>();
    softmax_k<<<NT, 256>>>();
    av_k<<<dim3(8, 80), 256, SMEM_T>>>(out);
    reduce_k<<<NT - 1024, 256>>>(out);
}

// round 9
// speedup vs baseline: 1.2305x; 1.0782x over previous
#include <cuda_runtime.h>
#include <cuda_fp16.h>
#include <cstdint>

#define NT 4096
#define DI 1024

// ---- scratch (__device__ globals per allocation rules) ----
__device__ __half g_X[NT * DI];           // fp16 x
__device__ __half g_Q[NT * DI];           // fp16 Q
__device__ __half g_K[NT * DI];           // fp16 K
__device__ __half g_Vt[DI * NT];          // fp16 V^T (written directly by proj epilogue)
__device__ __half g_WT[3 * DI * DI];      // fp16 W^T
__device__ float  g_S[(size_t)NT * NT];   // fp32 scores
__device__ __half g_P[(size_t)NT * NT];   // fp16 probs (zero-padded tail)
__device__ float  g_Opart[3 * (size_t)NT * DI];  // split-K partials for av

// ============================ helpers ============================
__device__ __forceinline__ uint32_t smem_u32(const void* p) {
    uint32_t a;
    asm("{ .reg .u64 t; cvta.to.shared.u64 t, %1; cvt.u32.u64 %0, t; }" : "=r"(a) : "l"(p));
    return a;
}
__device__ __forceinline__ void cp16(uint32_t saddr, const void* g) {
    asm volatile("cp.async.cg.shared.global [%0], [%1], 16;" :: "r"(saddr), "l"(g));
}
__device__ __forceinline__ void cp_commit() { asm volatile("cp.async.commit_group;"); }
__device__ __forceinline__ void cp_wait2() { asm volatile("cp.async.wait_group 2;" ::: "memory"); }

__device__ __forceinline__ void mma_f16(float* c, const uint32_t* a, const uint32_t* b) {
    asm volatile(
        "mma.sync.aligned.m16n8k16.row.col.f32.f16.f16.f32 "
        "{%0,%1,%2,%3}, {%4,%5,%6,%7}, {%8,%9}, {%0,%1,%2,%3};"
        : "+f"(c[0]), "+f"(c[1]), "+f"(c[2]), "+f"(c[3])
        : "r"(a[0]), "r"(a[1]), "r"(a[2]), "r"(a[3]), "r"(b[0]), "r"(b[1]));
}
__device__ __forceinline__ void ldm_x4(uint32_t* r, uint32_t addr) {
    asm volatile("ldmatrix.sync.aligned.m8n8.x4.shared.b16 {%0,%1,%2,%3}, [%4];"
        : "=r"(r[0]), "=r"(r[1]), "=r"(r[2]), "=r"(r[3]) : "r"(addr));
}

// SMEM tile: rows of 32 halves (64B); 2 rows per 128B line; 16B chunks XOR-swizzled.
__device__ __forceinline__ uint32_t sw_chunk(int r, int q) {
    int line = r >> 1;
    int ch = (((r & 1) << 2) | q) ^ (line & 7);
    return (uint32_t)(line * 128 + ch * 16);
}

// ============================ GEMM ============================
#define BM 128
#define BN 128
#define BK 32
#define A_BYTES (BM * 64)                 // 8192
#define STAGE_BYTES (A_BYTES + BN * 64)   // 16384
#define NSTAGE 4
#define SMEM_T (NSTAGE * STAGE_BYTES)     // 65536

// MODE: 0 = fp32 row-major out, 1 = fp16 row-major out, 2 = fp16 transposed out (V^T)
// 4-buffer ring: load_stage(s+3) writes buffer (s+3)%4, last read at stage s-1
// (all warps past the stage-s top barrier) -> no post-compute barrier needed.
template <int MODE>
__device__ __forceinline__ void gemm_tile(
    const __half* __restrict__ A, int lda,
    const __half* __restrict__ B, int ldb,
    int row0, int col0, int kLen,
    float scale, const float* __restrict__ bias,
    void* __restrict__ Out, int ldo)
{
    constexpr int NI = 4;

    extern __shared__ char sm[];
    const uint32_t sb = smem_u32(sm);
    const int tid  = threadIdx.x;
    const int lane = tid & 31;
    const int warp = tid >> 5;
    const int wm = warp >> 2;       // 0..1
    const int wn = warp & 3;        // 0..3

    float acc[4][NI][4];
#pragma unroll
    for (int mi = 0; mi < 4; mi++)
#pragma unroll
        for (int ni = 0; ni < NI; ni++)
#pragma unroll
            for (int q = 0; q < 4; q++) acc[mi][ni][q] = 0.f;

    const int nStages = kLen / BK;   // >= 4 in all uses

    auto load_stage = [&](int s) {
        const uint32_t base = sb + (uint32_t)((s & (NSTAGE - 1)) * STAGE_BYTES);
        const int k0 = s * BK;
#pragma unroll
        for (int i = 0; i < 2; i++) {
            int idx = tid + i * 256;
            int r = idx >> 2, q = idx & 3;
            cp16(base + sw_chunk(r, q),
                 A + (size_t)(row0 + r) * lda + k0 + q * 8);
        }
#pragma unroll
        for (int i = 0; i < 2; i++) {
            int idx = tid + i * 256;
            int r = idx >> 2, q = idx & 3;
            cp16(base + A_BYTES + sw_chunk(r, q),
                 B + (size_t)(col0 + r) * ldb + k0 + q * 8);
        }
        cp_commit();
    };

    load_stage(0);
    load_stage(1);
    load_stage(2);

    // per-lane ldmatrix row components (stage/k16-invariant)
    const int laneA_r = wm * 64 + (lane & 7) + ((lane >> 3) & 1) * 8;  // + mi*16
    const int laneA_q = lane >> 4;                                     // + k16*2
    const int laneB_r7 = lane & 7;
    const int laneB_sub = lane >> 3;        // 0..3

    for (int s = 0; s < nStages; s++) {
        cp_wait2();
        __syncthreads();
        const uint32_t abase = sb + (uint32_t)((s & (NSTAGE - 1)) * STAGE_BYTES);
        const uint32_t bbase = abase + A_BYTES;
#pragma unroll
        for (int k16 = 0; k16 < 2; k16++) {
            uint32_t af[4][4], bf[NI][2];
#pragma unroll
            for (int mi = 0; mi < 4; mi++)
                ldm_x4(af[mi], abase + sw_chunk(laneA_r + mi * 16, k16 * 2 + laneA_q));
#pragma unroll
            for (int p = 0; p < NI / 2; p++) {
                const int nrow = wn * (NI * 8) + (p * 2 + (laneB_sub >> 1)) * 8 + laneB_r7;
                const int qb = k16 * 2 + (laneB_sub & 1);
                uint32_t t[4];
                ldm_x4(t, bbase + sw_chunk(nrow, qb));
                bf[p * 2][0] = t[0]; bf[p * 2][1] = t[1];
                bf[p * 2 + 1][0] = t[2]; bf[p * 2 + 1][1] = t[3];
            }
#pragma unroll
            for (int mi = 0; mi < 4; mi++)
#pragma unroll
                for (int ni = 0; ni < NI; ni++)
                    mma_f16(acc[mi][ni], af[mi], bf[ni]);
        }
        // no barrier here: 4-buffer ring makes (s+3)%4 safe to overwrite
        if (s + 3 < nStages) load_stage(s + 3);
        else cp_commit();
    }

    // epilogue
#pragma unroll
    for (int mi = 0; mi < 4; mi++) {
#pragma unroll
        for (int ni = 0; ni < NI; ni++) {
            const int row = row0 + wm * 64 + mi * 16 + (lane >> 2);
            const int col = col0 + wn * (NI * 8) + ni * 8 + 2 * (lane & 3);
            float v00 = acc[mi][ni][0] * scale, v01 = acc[mi][ni][1] * scale;
            float v10 = acc[mi][ni][2] * scale, v11 = acc[mi][ni][3] * scale;
            if (bias) {
                const float b0 = bias[col], b1 = bias[col + 1];
                v00 += b0; v01 += b1; v10 += b0; v11 += b1;
            }
            if (MODE == 0) {
                *(float2*)((float*)Out + (size_t)row * ldo + col)       = make_float2(v00, v01);
                *(float2*)((float*)Out + (size_t)(row + 8) * ldo + col) = make_float2(v10, v11);
            } else if (MODE == 1) {
                *(__half2*)((__half*)Out + (size_t)row * ldo + col)       = __floats2half2_rn(v00, v01);
                *(__half2*)((__half*)Out + (size_t)(row + 8) * ldo + col) = __floats2half2_rn(v10, v11);
            } else {
                // transposed fp16: Out[col][row] with leading dim ldo
                __half* o = (__half*)Out;
                o[(size_t)col * ldo + row]           = __float2half_rn(v00);
                o[(size_t)(col + 1) * ldo + row]     = __float2half_rn(v01);
                o[(size_t)col * ldo + row + 8]       = __float2half_rn(v10);
                o[(size_t)(col + 1) * ldo + row + 8] = __float2half_rn(v11);
            }
        }
    }
}

// ============================ kernels ============================
// one launch for all three projections; z=2 writes V^T directly
__global__ __launch_bounds__(256, 2) void proj_k(
    const float* __restrict__ bq, const float* __restrict__ bk, const float* __restrict__ bv)
{
    const int z = blockIdx.z;
    const __half* W = g_WT + (size_t)z * DI * DI;
    const int r0 = blockIdx.y * BM, c0 = blockIdx.x * BN;
    if (z == 0)
        gemm_tile<1>(g_X, DI, W, DI, r0, c0, DI, 1.0f, bq, g_Q, DI);
    else if (z == 1)
        gemm_tile<1>(g_X, DI, W, DI, r0, c0, DI, 1.0f, bk, g_K, DI);
    else
        gemm_tile<2>(g_X, DI, W, DI, r0, c0, DI, 1.0f, bv, g_Vt, NT);
}

__global__ __launch_bounds__(256, 2) void score_k()
{
    // lower-tri 128x128 blocks: count(rt) = rt+1, total 528
    int b = blockIdx.x, rt = 0;
    while (b > rt) { b -= rt + 1; rt++; }
    gemm_tile<0>(g_Q, DI, g_K, DI, rt * BM, b * BN, DI, 0.03125f,
                 nullptr, g_S, NT);
}

// split-K av: chunks of <=1024 K. blockIdx.y in [0,80) -> (rt, kc).
__global__ __launch_bounds__(256, 2) void av_k(float* __restrict__ out)
{
    int y = blockIdx.y, rt = 0;
    while (y >= ((rt >> 3) + 1)) { y -= (rt >> 3) + 1; rt++; }
    const int kc = y;
    const int kStart = kc << 10;
    const int kEndFull = (rt + 1) << 7;
    const int kLen = min(kEndFull, kStart + 1024) - kStart;

    float* dst = (kc == 0) ? out : (g_Opart + (size_t)(kc - 1) * NT * DI);
    gemm_tile<0>(g_P + kStart, NT, g_Vt + kStart, NT,
                 rt * BM, blockIdx.x * BN, kLen, 1.0f, nullptr, dst, DI);
}

// fold split-K partials into out (rows with rt>=8 only), fixed order
__global__ __launch_bounds__(256) void reduce_k(float* __restrict__ out)
{
    const int row = 1024 + blockIdx.x;
    const int tid = threadIdx.x;
    const int nextra = (row >> 7) >> 3;   // 1..3
    float4* o4 = (float4*)(out + (size_t)row * DI) + tid;
    float4 v = *o4;
    for (int j = 0; j < nextra; j++) {
        const float4 p = *((const float4*)(g_Opart + (size_t)j * NT * DI + (size_t)row * DI) + tid);
        v.x += p.x; v.y += p.y; v.z += p.z; v.w += p.w;
    }
    *o4 = v;
}

__global__ void cvt_x_k(const float* __restrict__ x)
{
    const int i = blockIdx.x * blockDim.x + threadIdx.x;   // float4 index
    float4 v = ((const float4*)x)[i];
    __half2* d = (__half2*)(g_X + i * 4);
    d[0] = __floats2half2_rn(v.x, v.y);
    d[1] = __floats2half2_rn(v.z, v.w);
}

__global__ void transW_k(const float* __restrict__ Wq, const float* __restrict__ Wk,
                         const float* __restrict__ Wv)
{
    const float* in = (blockIdx.z == 0) ? Wq : (blockIdx.z == 1) ? Wk : Wv;
    __half* out = g_WT + (size_t)blockIdx.z * DI * DI;
    __shared__ float t[32][33];
    const int c0 = blockIdx.x * 32, r0 = blockIdx.y * 32;
    const int tx = threadIdx.x, ty = threadIdx.y;
#pragma unroll
    for (int j = 0; j < 32; j += 8) t[ty + j][tx] = in[(size_t)(r0 + ty + j) * DI + c0 + tx];
    __syncthreads();
#pragma unroll
    for (int j = 0; j < 32; j += 8)
        out[(size_t)(c0 + ty + j) * DI + r0 + tx] = __float2half_rn(t[tx][ty + j]);
}

// causal row softmax: read fp32 S, write fp16 probs with zero tail
__global__ __launch_bounds__(256) void softmax_k()
{
    __shared__ float buf[NT];
    __shared__ float red[256];
    const int i = blockIdx.x;
    const int valid = i + 1;
    const int tid = threadIdx.x;
    const float* row = g_S + (size_t)i * NT;
    __half* prow = g_P + (size_t)i * NT;

    float m = -1e30f;
    for (int j = tid; j < valid; j += 256) {
        float v = row[j];
        buf[j] = v;
        m = fmaxf(m, v);
    }
    red[tid] = m; __syncthreads();
    for (int s = 128; s > 0; s >>= 1) { if (tid < s) red[tid] = fmaxf(red[tid], red[tid + s]); __syncthreads(); }
    m = red[0]; __syncthreads();

    float sum = 0.f;
    for (int j = tid; j < valid; j += 256) {
        float e = __expf(buf[j] - m);
        buf[j] = e;
        sum += e;
    }
    red[tid] = sum; __syncthreads();
    for (int s = 128; s > 0; s >>= 1) { if (tid < s) red[tid] += red[tid + s]; __syncthreads(); }
    const float inv = 1.0f / red[0];
    __syncthreads();

    for (int j = tid; j < valid; j += 256) prow[j] = __float2half_rn(buf[j] * inv);
    for (int j = valid + tid; j < NT; j += 256) prow[j] = __float2half_rn(0.f);
}

// ============================ launch ============================
extern "C" void kernel_launch(void* const* d_in, const int* in_sizes, int n_in,
                              void* d_out, int out_size)
{
    const float* x  = (const float*)d_in[0];
    const float* Wq = (const float*)d_in[1];
    const float* bq = (const float*)d_in[2];
    const float* Wk = (const float*)d_in[3];
    const float* bk = (const float*)d_in[4];
    const float* Wv = (const float*)d_in[5];
    const float* bv = (const float*)d_in[6];
    float* out = (float*)d_out;

    cudaFuncSetAttribute(proj_k,  cudaFuncAttributeMaxDynamicSharedMemorySize, SMEM_T);
    cudaFuncSetAttribute(score_k, cudaFuncAttributeMaxDynamicSharedMemorySize, SMEM_T);
    cudaFuncSetAttribute(av_k,    cudaFuncAttributeMaxDynamicSharedMemorySize, SMEM_T);

    cvt_x_k<<<NT * DI / 4 / 256, 256>>>(x);
    transW_k<<<dim3(32, 32, 3), dim3(32, 8)>>>(Wq, Wk, Wv);
    proj_k<<<dim3(8, 32, 3), 256, SMEM_T>>>(bq, bk, bv);
    score_k<<<528, 256, SMEM_T>>>();
    softmax_k<<<NT, 256>>>();
    av_k<<<dim3(8, 80), 256, SMEM_T>>>(out);
    reduce_k<<<NT - 1024, 256>>>(out);
}

// round 11
// speedup vs baseline: 1.3534x; 1.0998x over previous
#include <cuda_runtime.h>
#include <cuda_fp16.h>
#include <cstdint>

#define NT 4096
#define DI 1024

// ---- scratch (__device__ globals per allocation rules) ----
__device__ __half g_X[NT * DI];           // fp16 x
__device__ __half g_Q[NT * DI];           // fp16 Q
__device__ __half g_K[NT * DI];           // fp16 K
__device__ __half g_Vt[DI * NT];          // fp16 V^T (written directly by proj epilogue)
__device__ __half g_WT[3 * DI * DI];      // fp16 W^T
__device__ float  g_S[(size_t)NT * NT];   // fp32 scores
__device__ __half g_P[(size_t)NT * NT];   // fp16 probs (zero-padded tail)
__device__ float  g_Opart[3 * (size_t)NT * DI];  // split-K partials for av

// ============================ helpers ============================
__device__ __forceinline__ uint32_t smem_u32(const void* p) {
    uint32_t a;
    asm("{ .reg .u64 t; cvta.to.shared.u64 t, %1; cvt.u32.u64 %0, t; }" : "=r"(a) : "l"(p));
    return a;
}
__device__ __forceinline__ void cp16(uint32_t saddr, const void* g) {
    asm volatile("cp.async.cg.shared.global [%0], [%1], 16;" :: "r"(saddr), "l"(g));
}
__device__ __forceinline__ void cp_commit() { asm volatile("cp.async.commit_group;"); }
__device__ __forceinline__ void cp_wait1() { asm volatile("cp.async.wait_group 1;" ::: "memory"); }

__device__ __forceinline__ void mma_f16(float* c, const uint32_t* a, const uint32_t* b) {
    asm volatile(
        "mma.sync.aligned.m16n8k16.row.col.f32.f16.f16.f32 "
        "{%0,%1,%2,%3}, {%4,%5,%6,%7}, {%8,%9}, {%0,%1,%2,%3};"
        : "+f"(c[0]), "+f"(c[1]), "+f"(c[2]), "+f"(c[3])
        : "r"(a[0]), "r"(a[1]), "r"(a[2]), "r"(a[3]), "r"(b[0]), "r"(b[1]));
}
__device__ __forceinline__ void ldm_x4(uint32_t* r, uint32_t addr) {
    asm volatile("ldmatrix.sync.aligned.m8n8.x4.shared.b16 {%0,%1,%2,%3}, [%4];"
        : "=r"(r[0]), "=r"(r[1]), "=r"(r[2]), "=r"(r[3]) : "r"(addr));
}

// SMEM tile: rows of 64 halves = 128B line each; canonical SW128 swizzle:
// 16B chunk q of row r stored at chunk (q ^ (r & 7)).
__device__ __forceinline__ uint32_t sw64(int r, int q) {
    return (uint32_t)(r * 128 + ((q ^ (r & 7)) << 4));
}

// ============================ GEMM ============================
#define BM 128
#define BN 128
#define BK 64
#define A_BYTES (BM * 128)                // 16384
#define STAGE_BYTES (A_BYTES + BN * 128)  // 32768
#define NSTAGE 3
#define SMEM_T (NSTAGE * STAGE_BYTES)     // 98304

// MODE: 0 = fp32 row-major out, 1 = fp16 row-major out, 2 = fp16 transposed out (V^T)
// 3-buffer ring, prefetch 2 ahead, wait_group 1, no post-compute barrier:
// load_stage(s+2) writes buffer (s+2)%3, last read at stage s-1 (all warps past
// the stage-s top barrier).
template <int MODE>
__device__ __forceinline__ void gemm_tile(
    const __half* __restrict__ A, int lda,
    const __half* __restrict__ B, int ldb,
    int row0, int col0, int kLen,
    float scale, const float* __restrict__ bias,
    void* __restrict__ Out, int ldo)
{
    constexpr int NI = 4;

    extern __shared__ char sm[];
    const uint32_t sb = smem_u32(sm);
    const int tid  = threadIdx.x;
    const int lane = tid & 31;
    const int warp = tid >> 5;
    const int wm = warp >> 2;       // 0..1
    const int wn = warp & 3;        // 0..3

    float acc[4][NI][4];
#pragma unroll
    for (int mi = 0; mi < 4; mi++)
#pragma unroll
        for (int ni = 0; ni < NI; ni++)
#pragma unroll
            for (int q = 0; q < 4; q++) acc[mi][ni][q] = 0.f;

    const int nStages = kLen / BK;   // >= 2 in all uses

    auto load_stage = [&](int s) {
        const uint32_t base = sb + (uint32_t)((s % NSTAGE) * STAGE_BYTES);
        const int k0 = s * BK;
        // A: 128 rows x 8 chunks of 16B
#pragma unroll
        for (int i = 0; i < 4; i++) {
            int idx = tid + i * 256;
            int r = idx >> 3, q = idx & 7;
            cp16(base + sw64(r, q),
                 A + (size_t)(row0 + r) * lda + k0 + q * 8);
        }
        // B: 128 rows x 8 chunks
#pragma unroll
        for (int i = 0; i < 4; i++) {
            int idx = tid + i * 256;
            int r = idx >> 3, q = idx & 7;
            cp16(base + A_BYTES + sw64(r, q),
                 B + (size_t)(col0 + r) * ldb + k0 + q * 8);
        }
        cp_commit();
    };

    load_stage(0);
    load_stage(1);

    // per-lane ldmatrix row components (stage/k16-invariant)
    const int laneA_r = wm * 64 + (lane & 7) + ((lane >> 3) & 1) * 8;  // + mi*16
    const int laneA_q = lane >> 4;                                     // + k16*2
    const int laneB_r7 = lane & 7;
    const int laneB_sub = lane >> 3;        // 0..3

    for (int s = 0; s < nStages; s++) {
        cp_wait1();
        __syncthreads();
        const uint32_t abase = sb + (uint32_t)((s % NSTAGE) * STAGE_BYTES);
        const uint32_t bbase = abase + A_BYTES;
#pragma unroll
        for (int k16 = 0; k16 < 4; k16++) {
            uint32_t af[4][4], bf[NI][2];
#pragma unroll
            for (int mi = 0; mi < 4; mi++) {
                const int r = laneA_r + mi * 16;
                ldm_x4(af[mi], abase + sw64(r, k16 * 2 + laneA_q));
            }
#pragma unroll
            for (int p = 0; p < NI / 2; p++) {
                const int nrow = wn * (NI * 8) + (p * 2 + (laneB_sub >> 1)) * 8 + laneB_r7;
                const int qb = k16 * 2 + (laneB_sub & 1);
                uint32_t t[4];
                ldm_x4(t, bbase + sw64(nrow, qb));
                bf[p * 2][0] = t[0]; bf[p * 2][1] = t[1];
                bf[p * 2 + 1][0] = t[2]; bf[p * 2 + 1][1] = t[3];
            }
#pragma unroll
            for (int mi = 0; mi < 4; mi++)
#pragma unroll
                for (int ni = 0; ni < NI; ni++)
                    mma_f16(acc[mi][ni], af[mi], bf[ni]);
        }
        // no barrier: ring distance 2 with 3 buffers is safe
        if (s + 2 < nStages) load_stage(s + 2);
        else cp_commit();
    }

    // epilogue
#pragma unroll
    for (int mi = 0; mi < 4; mi++) {
#pragma unroll
        for (int ni = 0; ni < NI; ni++) {
            const int row = row0 + wm * 64 + mi * 16 + (lane >> 2);
            const int col = col0 + wn * (NI * 8) + ni * 8 + 2 * (lane & 3);
            float v00 = acc[mi][ni][0] * scale, v01 = acc[mi][ni][1] * scale;
            float v10 = acc[mi][ni][2] * scale, v11 = acc[mi][ni][3] * scale;
            if (bias) {
                const float b0 = bias[col], b1 = bias[col + 1];
                v00 += b0; v01 += b1; v10 += b0; v11 += b1;
            }
            if (MODE == 0) {
                *(float2*)((float*)Out + (size_t)row * ldo + col)       = make_float2(v00, v01);
                *(float2*)((float*)Out + (size_t)(row + 8) * ldo + col) = make_float2(v10, v11);
            } else if (MODE == 1) {
                *(__half2*)((__half*)Out + (size_t)row * ldo + col)       = __floats2half2_rn(v00, v01);
                *(__half2*)((__half*)Out + (size_t)(row + 8) * ldo + col) = __floats2half2_rn(v10, v11);
            } else {
                __half* o = (__half*)Out;
                o[(size_t)col * ldo + row]           = __float2half_rn(v00);
                o[(size_t)(col + 1) * ldo + row]     = __float2half_rn(v01);
                o[(size_t)col * ldo + row + 8]       = __float2half_rn(v10);
                o[(size_t)(col + 1) * ldo + row + 8] = __float2half_rn(v11);
            }
        }
    }
}

// ============================ kernels ============================
__global__ __launch_bounds__(256, 2) void proj_k(
    const float* __restrict__ bq, const float* __restrict__ bk, const float* __restrict__ bv)
{
    const int z = blockIdx.z;
    const __half* W = g_WT + (size_t)z * DI * DI;
    const int r0 = blockIdx.y * BM, c0 = blockIdx.x * BN;
    if (z == 0)
        gemm_tile<1>(g_X, DI, W, DI, r0, c0, DI, 1.0f, bq, g_Q, DI);
    else if (z == 1)
        gemm_tile<1>(g_X, DI, W, DI, r0, c0, DI, 1.0f, bk, g_K, DI);
    else
        gemm_tile<2>(g_X, DI, W, DI, r0, c0, DI, 1.0f, bv, g_Vt, NT);
}

__global__ __launch_bounds__(256, 2) void score_k()
{
    int b = blockIdx.x, rt = 0;
    while (b > rt) { b -= rt + 1; rt++; }
    gemm_tile<0>(g_Q, DI, g_K, DI, rt * BM, b * BN, DI, 0.03125f,
                 nullptr, g_S, NT);
}

// split-K av: chunks of <=1024 K. blockIdx.y in [0,80) -> (rt, kc).
__global__ __launch_bounds__(256, 2) void av_k(float* __restrict__ out)
{
    int y = blockIdx.y, rt = 0;
    while (y >= ((rt >> 3) + 1)) { y -= (rt >> 3) + 1; rt++; }
    const int kc = y;
    const int kStart = kc << 10;
    const int kEndFull = (rt + 1) << 7;
    const int kLen = min(kEndFull, kStart + 1024) - kStart;

    float* dst = (kc == 0) ? out : (g_Opart + (size_t)(kc - 1) * NT * DI);
    gemm_tile<0>(g_P + kStart, NT, g_Vt + kStart, NT,
                 rt * BM, blockIdx.x * BN, kLen, 1.0f, nullptr, dst, DI);
}

__global__ __launch_bounds__(256) void reduce_k(float* __restrict__ out)
{
    const int row = 1024 + blockIdx.x;
    const int tid = threadIdx.x;
    const int nextra = (row >> 7) >> 3;   // 1..3
    float4* o4 = (float4*)(out + (size_t)row * DI) + tid;
    float4 v = *o4;
    for (int j = 0; j < nextra; j++) {
        const float4 p = *((const float4*)(g_Opart + (size_t)j * NT * DI + (size_t)row * DI) + tid);
        v.x += p.x; v.y += p.y; v.z += p.z; v.w += p.w;
    }
    *o4 = v;
}

__global__ void cvt_x_k(const float* __restrict__ x)
{
    const int i = blockIdx.x * blockDim.x + threadIdx.x;
    float4 v = ((const float4*)x)[i];
    __half2* d = (__half2*)(g_X + i * 4);
    d[0] = __floats2half2_rn(v.x, v.y);
    d[1] = __floats2half2_rn(v.z, v.w);
}

__global__ void transW_k(const float* __restrict__ Wq, const float* __restrict__ Wk,
                         const float* __restrict__ Wv)
{
    const float* in = (blockIdx.z == 0) ? Wq : (blockIdx.z == 1) ? Wk : Wv;
    __half* out = g_WT + (size_t)blockIdx.z * DI * DI;
    __shared__ float t[32][33];
    const int c0 = blockIdx.x * 32, r0 = blockIdx.y * 32;
    const int tx = threadIdx.x, ty = threadIdx.y;
#pragma unroll
    for (int j = 0; j < 32; j += 8) t[ty + j][tx] = in[(size_t)(r0 + ty + j) * DI + c0 + tx];
    __syncthreads();
#pragma unroll
    for (int j = 0; j < 32; j += 8)
        out[(size_t)(c0 + ty + j) * DI + r0 + tx] = __float2half_rn(t[tx][ty + j]);
}

// causal row softmax: float4 loads, warp-shuffle reductions, half2 stores
__global__ __launch_bounds__(256) void softmax_k()
{
    __shared__ float buf[NT];
    __shared__ float wred[8];
    const int i = blockIdx.x;
    const int valid = i + 1;
    const int tid = threadIdx.x;
    const int lane = tid & 31, w = tid >> 5;
    const float* row = g_S + (size_t)i * NT;
    __half* prow = g_P + (size_t)i * NT;

    const int nvec = (valid + 3) >> 2;          // float4 count covering valid

    // pass 1: load + max
    float m = -1e30f;
    for (int j = tid; j < nvec; j += 256) {
        float4 v = ((const float4*)row)[j];
        const int base = j * 4;
        if (base + 3 >= valid) {                 // mask tail inside last vector
            if (base + 1 >= valid) v.y = -1e30f;
            if (base + 2 >= valid) v.z = -1e30f;
            v.w = (base + 3 < valid) ? v.w : -1e30f;
        }
        *(float4*)(buf + base) = v;
        m = fmaxf(fmaxf(m, fmaxf(v.x, v.y)), fmaxf(v.z, v.w));
    }
#pragma unroll
    for (int o = 16; o > 0; o >>= 1) m = fmaxf(m, __shfl_xor_sync(0xffffffffu, m, o));
    if (lane == 0) wred[w] = m;
    __syncthreads();
    m = wred[0];
#pragma unroll
    for (int q = 1; q < 8; q++) m = fmaxf(m, wred[q]);

    // pass 2: exp + sum (buf tail already -1e30 -> exp ~ 0)
    float sum = 0.f;
    for (int j = tid; j < nvec; j += 256) {
        float4 v = *(float4*)(buf + j * 4);
        v.x = __expf(v.x - m); v.y = __expf(v.y - m);
        v.z = __expf(v.z - m); v.w = __expf(v.w - m);
        *(float4*)(buf + j * 4) = v;
        sum += v.x + v.y + v.z + v.w;
    }
#pragma unroll
    for (int o = 16; o > 0; o >>= 1) sum += __shfl_xor_sync(0xffffffffu, sum, o);
    __syncthreads();                 // wred reuse
    if (lane == 0) wred[w] = sum;
    __syncthreads();
    sum = 0.f;
#pragma unroll
    for (int q = 0; q < 8; q++) sum += wred[q];
    const float inv = 1.0f / sum;

    // pass 3: normalized fp16 store (4 halves per op); zero tail
    for (int j = tid; j < nvec; j += 256) {
        float4 v = *(float4*)(buf + j * 4);
        __half2 h0 = __floats2half2_rn(v.x * inv, v.y * inv);
        __half2 h1 = __floats2half2_rn(v.z * inv, v.w * inv);
        uint2 u;
        u.x = *(uint32_t*)&h0;
        u.y = *(uint32_t*)&h1;
        ((uint2*)prow)[j] = u;
    }
    for (int j = nvec + tid; j < NT / 4; j += 256)
        ((uint2*)prow)[j] = make_uint2(0u, 0u);
}

// ============================ launch ============================
extern "C" void kernel_launch(void* const* d_in, const int* in_sizes, int n_in,
                              void* d_out, int out_size)
{
    const float* x  = (const float*)d_in[0];
    const float* Wq = (const float*)d_in[1];
    const float* bq = (const float*)d_in[2];
    const float* Wk = (const float*)d_in[3];
    const float* bk = (const float*)d_in[4];
    const float* Wv = (const float*)d_in[5];
    const float* bv = (const float*)d_in[6];
    float* out = (float*)d_out;

    cudaFuncSetAttribute(proj_k,  cudaFuncAttributeMaxDynamicSharedMemorySize, SMEM_T);
    cudaFuncSetAttribute(score_k, cudaFuncAttributeMaxDynamicSharedMemorySize, SMEM_T);
    cudaFuncSetAttribute(av_k,    cudaFuncAttributeMaxDynamicSharedMemorySize, SMEM_T);

    cvt_x_k<<<NT * DI / 4 / 256, 256>>>(x);
    transW_k<<<dim3(32, 32, 3), dim3(32, 8)>>>(Wq, Wk, Wv);
    proj_k<<<dim3(8, 32, 3), 256, SMEM_T>>>(bq, bk, bv);
    score_k<<<528, 256, SMEM_T>>>();
    softmax_k<<<NT, 256>>>();
    av_k<<<dim3(8, 80), 256, SMEM_T>>>(out);
    reduce_k<<<NT - 1024, 256>>>(out);
}

// round 12
// speedup vs baseline: 1.4522x; 1.0730x over previous
#include <cuda_runtime.h>
#include <cuda_fp16.h>
#include <cstdint>

#define NT 4096
#define DI 1024

// ---- scratch (__device__ globals per allocation rules) ----
__device__ __half g_X[NT * DI];           // fp16 x
__device__ __half g_Q[NT * DI];           // fp16 Q
__device__ __half g_K[NT * DI];           // fp16 K
__device__ __half g_Vt[DI * NT];          // fp16 V^T (written directly by proj epilogue)
__device__ __half g_WT[3 * DI * DI];      // fp16 W^T
__device__ float  g_S[(size_t)NT * NT];   // fp32 scores
__device__ __half g_P[(size_t)NT * NT];   // fp16 probs (zero-padded tail)
__device__ float  g_Opart[3 * (size_t)NT * DI];  // split-K partials for av

// ============================ helpers ============================
__device__ __forceinline__ uint32_t smem_u32(const void* p) {
    uint32_t a;
    asm("{ .reg .u64 t; cvta.to.shared.u64 t, %1; cvt.u32.u64 %0, t; }" : "=r"(a) : "l"(p));
    return a;
}
__device__ __forceinline__ void cp16(uint32_t saddr, const void* g) {
    asm volatile("cp.async.cg.shared.global [%0], [%1], 16;" :: "r"(saddr), "l"(g));
}
__device__ __forceinline__ void cp_commit() { asm volatile("cp.async.commit_group;"); }
__device__ __forceinline__ void cp_wait1() { asm volatile("cp.async.wait_group 1;" ::: "memory"); }

__device__ __forceinline__ void mma_f16(float* c, const uint32_t* a, const uint32_t* b) {
    asm volatile(
        "mma.sync.aligned.m16n8k16.row.col.f32.f16.f16.f32 "
        "{%0,%1,%2,%3}, {%4,%5,%6,%7}, {%8,%9}, {%0,%1,%2,%3};"
        : "+f"(c[0]), "+f"(c[1]), "+f"(c[2]), "+f"(c[3])
        : "r"(a[0]), "r"(a[1]), "r"(a[2]), "r"(a[3]), "r"(b[0]), "r"(b[1]));
}
__device__ __forceinline__ void ldm_x4(uint32_t* r, uint32_t addr) {
    asm volatile("ldmatrix.sync.aligned.m8n8.x4.shared.b16 {%0,%1,%2,%3}, [%4];"
        : "=r"(r[0]), "=r"(r[1]), "=r"(r[2]), "=r"(r[3]) : "r"(addr));
}

// SMEM tile: rows of 64 halves = 128B line each; canonical SW128 swizzle.
__device__ __forceinline__ uint32_t sw64(int r, int q) {
    return (uint32_t)(r * 128 + ((q ^ (r & 7)) << 4));
}

// ============================ GEMM ============================
#define BM 128
#define BN 128
#define BK 64
#define A_BYTES (BM * 128)                // 16384
#define STAGE_BYTES (A_BYTES + BN * 128)  // 32768
#define NSTAGE 3
#define SMEM_T (NSTAGE * STAGE_BYTES)     // 98304

// MODE: 0 = fp32 row-major out, 1 = fp16 row-major out, 2 = fp16 transposed out (V^T)
template <int MODE>
__device__ __forceinline__ void gemm_tile(
    const __half* __restrict__ A, int lda,
    const __half* __restrict__ B, int ldb,
    int row0, int col0, int kLen,
    float scale, const float* __restrict__ bias,
    void* __restrict__ Out, int ldo)
{
    constexpr int NI = 4;

    extern __shared__ char sm[];
    const uint32_t sb = smem_u32(sm);
    const int tid  = threadIdx.x;
    const int lane = tid & 31;
    const int warp = tid >> 5;
    const int wm = warp >> 2;
    const int wn = warp & 3;

    float acc[4][NI][4];
#pragma unroll
    for (int mi = 0; mi < 4; mi++)
#pragma unroll
        for (int ni = 0; ni < NI; ni++)
#pragma unroll
            for (int q = 0; q < 4; q++) acc[mi][ni][q] = 0.f;

    const int nStages = kLen / BK;

    auto load_stage = [&](int s) {
        const uint32_t base = sb + (uint32_t)((s % NSTAGE) * STAGE_BYTES);
        const int k0 = s * BK;
#pragma unroll
        for (int i = 0; i < 4; i++) {
            int idx = tid + i * 256;
            int r = idx >> 3, q = idx & 7;
            cp16(base + sw64(r, q),
                 A + (size_t)(row0 + r) * lda + k0 + q * 8);
        }
#pragma unroll
        for (int i = 0; i < 4; i++) {
            int idx = tid + i * 256;
            int r = idx >> 3, q = idx & 7;
            cp16(base + A_BYTES + sw64(r, q),
                 B + (size_t)(col0 + r) * ldb + k0 + q * 8);
        }
        cp_commit();
    };

    load_stage(0);
    load_stage(1);

    const int laneA_r = wm * 64 + (lane & 7) + ((lane >> 3) & 1) * 8;
    const int laneA_q = lane >> 4;
    const int laneB_r7 = lane & 7;
    const int laneB_sub = lane >> 3;

    for (int s = 0; s < nStages; s++) {
        cp_wait1();
        __syncthreads();
        const uint32_t abase = sb + (uint32_t)((s % NSTAGE) * STAGE_BYTES);
        const uint32_t bbase = abase + A_BYTES;
#pragma unroll
        for (int k16 = 0; k16 < 4; k16++) {
            uint32_t af[4][4], bf[NI][2];
#pragma unroll
            for (int mi = 0; mi < 4; mi++) {
                const int r = laneA_r + mi * 16;
                ldm_x4(af[mi], abase + sw64(r, k16 * 2 + laneA_q));
            }
#pragma unroll
            for (int p = 0; p < NI / 2; p++) {
                const int nrow = wn * (NI * 8) + (p * 2 + (laneB_sub >> 1)) * 8 + laneB_r7;
                const int qb = k16 * 2 + (laneB_sub & 1);
                uint32_t t[4];
                ldm_x4(t, bbase + sw64(nrow, qb));
                bf[p * 2][0] = t[0]; bf[p * 2][1] = t[1];
                bf[p * 2 + 1][0] = t[2]; bf[p * 2 + 1][1] = t[3];
            }
#pragma unroll
            for (int mi = 0; mi < 4; mi++)
#pragma unroll
                for (int ni = 0; ni < NI; ni++)
                    mma_f16(acc[mi][ni], af[mi], bf[ni]);
        }
        if (s + 2 < nStages) load_stage(s + 2);
        else cp_commit();
    }

    // epilogue
#pragma unroll
    for (int mi = 0; mi < 4; mi++) {
#pragma unroll
        for (int ni = 0; ni < NI; ni++) {
            const int row = row0 + wm * 64 + mi * 16 + (lane >> 2);
            const int col = col0 + wn * (NI * 8) + ni * 8 + 2 * (lane & 3);
            float v00 = acc[mi][ni][0] * scale, v01 = acc[mi][ni][1] * scale;
            float v10 = acc[mi][ni][2] * scale, v11 = acc[mi][ni][3] * scale;
            if (bias) {
                const float b0 = bias[col], b1 = bias[col + 1];
                v00 += b0; v01 += b1; v10 += b0; v11 += b1;
            }
            if (MODE == 0) {
                *(float2*)((float*)Out + (size_t)row * ldo + col)       = make_float2(v00, v01);
                *(float2*)((float*)Out + (size_t)(row + 8) * ldo + col) = make_float2(v10, v11);
            } else if (MODE == 1) {
                *(__half2*)((__half*)Out + (size_t)row * ldo + col)       = __floats2half2_rn(v00, v01);
                *(__half2*)((__half*)Out + (size_t)(row + 8) * ldo + col) = __floats2half2_rn(v10, v11);
            } else {
                __half* o = (__half*)Out;
                o[(size_t)col * ldo + row]           = __float2half_rn(v00);
                o[(size_t)(col + 1) * ldo + row]     = __float2half_rn(v01);
                o[(size_t)col * ldo + row + 8]       = __float2half_rn(v10);
                o[(size_t)(col + 1) * ldo + row + 8] = __float2half_rn(v11);
            }
        }
    }
}

// ============================ kernels ============================
// Q and K projections only (z = 0,1) — main stream
__global__ __launch_bounds__(256, 2) void projQK_k(
    const float* __restrict__ bq, const float* __restrict__ bk)
{
    const int z = blockIdx.z;
    const __half* W = g_WT + (size_t)z * DI * DI;
    const int r0 = blockIdx.y * BM, c0 = blockIdx.x * BN;
    if (z == 0)
        gemm_tile<1>(g_X, DI, W, DI, r0, c0, DI, 1.0f, bq, g_Q, DI);
    else
        gemm_tile<1>(g_X, DI, W, DI, r0, c0, DI, 1.0f, bk, g_K, DI);
}

// V projection with fused transpose epilogue — side stream
__global__ __launch_bounds__(256, 2) void projV_k(const float* __restrict__ bv)
{
    gemm_tile<2>(g_X, DI, g_WT + (size_t)2 * DI * DI, DI,
                 blockIdx.y * BM, blockIdx.x * BN, DI, 1.0f, bv, g_Vt, NT);
}

__global__ __launch_bounds__(256, 2) void score_k()
{
    int b = blockIdx.x, rt = 0;
    while (b > rt) { b -= rt + 1; rt++; }
    gemm_tile<0>(g_Q, DI, g_K, DI, rt * BM, b * BN, DI, 0.03125f,
                 nullptr, g_S, NT);
}

// split-K av: chunks of <=1024 K. blockIdx.y in [0,80) -> (rt, kc).
__global__ __launch_bounds__(256, 2) void av_k(float* __restrict__ out)
{
    int y = blockIdx.y, rt = 0;
    while (y >= ((rt >> 3) + 1)) { y -= (rt >> 3) + 1; rt++; }
    const int kc = y;
    const int kStart = kc << 10;
    const int kEndFull = (rt + 1) << 7;
    const int kLen = min(kEndFull, kStart + 1024) - kStart;

    float* dst = (kc == 0) ? out : (g_Opart + (size_t)(kc - 1) * NT * DI);
    gemm_tile<0>(g_P + kStart, NT, g_Vt + kStart, NT,
                 rt * BM, blockIdx.x * BN, kLen, 1.0f, nullptr, dst, DI);
}

__global__ __launch_bounds__(256) void reduce_k(float* __restrict__ out)
{
    const int row = 1024 + blockIdx.x;
    const int tid = threadIdx.x;
    const int nextra = (row >> 7) >> 3;   // 1..3
    float4* o4 = (float4*)(out + (size_t)row * DI) + tid;
    float4 v = *o4;
    for (int j = 0; j < nextra; j++) {
        const float4 p = *((const float4*)(g_Opart + (size_t)j * NT * DI + (size_t)row * DI) + tid);
        v.x += p.x; v.y += p.y; v.z += p.z; v.w += p.w;
    }
    *o4 = v;
}

__global__ void cvt_x_k(const float* __restrict__ x)
{
    const int i = blockIdx.x * blockDim.x + threadIdx.x;
    float4 v = ((const float4*)x)[i];
    __half2* d = (__half2*)(g_X + i * 4);
    d[0] = __floats2half2_rn(v.x, v.y);
    d[1] = __floats2half2_rn(v.z, v.w);
}

__global__ void transW_k(const float* __restrict__ Wq, const float* __restrict__ Wk,
                         const float* __restrict__ Wv)
{
    const float* in = (blockIdx.z == 0) ? Wq : (blockIdx.z == 1) ? Wk : Wv;
    __half* out = g_WT + (size_t)blockIdx.z * DI * DI;
    __shared__ float t[32][33];
    const int c0 = blockIdx.x * 32, r0 = blockIdx.y * 32;
    const int tx = threadIdx.x, ty = threadIdx.y;
#pragma unroll
    for (int j = 0; j < 32; j += 8) t[ty + j][tx] = in[(size_t)(r0 + ty + j) * DI + c0 + tx];
    __syncthreads();
#pragma unroll
    for (int j = 0; j < 32; j += 8)
        out[(size_t)(c0 + ty + j) * DI + r0 + tx] = __float2half_rn(t[tx][ty + j]);
}

// causal row softmax: float4 loads, warp-shuffle reductions, half2 stores
__global__ __launch_bounds__(256) void softmax_k()
{
    __shared__ float buf[NT];
    __shared__ float wred[8];
    const int i = blockIdx.x;
    const int valid = i + 1;
    const int tid = threadIdx.x;
    const int lane = tid & 31, w = tid >> 5;
    const float* row = g_S + (size_t)i * NT;
    __half* prow = g_P + (size_t)i * NT;

    const int nvec = (valid + 3) >> 2;

    float m = -1e30f;
    for (int j = tid; j < nvec; j += 256) {
        float4 v = ((const float4*)row)[j];
        const int base = j * 4;
        if (base + 3 >= valid) {
            if (base + 1 >= valid) v.y = -1e30f;
            if (base + 2 >= valid) v.z = -1e30f;
            v.w = (base + 3 < valid) ? v.w : -1e30f;
        }
        *(float4*)(buf + base) = v;
        m = fmaxf(fmaxf(m, fmaxf(v.x, v.y)), fmaxf(v.z, v.w));
    }
#pragma unroll
    for (int o = 16; o > 0; o >>= 1) m = fmaxf(m, __shfl_xor_sync(0xffffffffu, m, o));
    if (lane == 0) wred[w] = m;
    __syncthreads();
    m = wred[0];
#pragma unroll
    for (int q = 1; q < 8; q++) m = fmaxf(m, wred[q]);

    float sum = 0.f;
    for (int j = tid; j < nvec; j += 256) {
        float4 v = *(float4*)(buf + j * 4);
        v.x = __expf(v.x - m); v.y = __expf(v.y - m);
        v.z = __expf(v.z - m); v.w = __expf(v.w - m);
        *(float4*)(buf + j * 4) = v;
        sum += v.x + v.y + v.z + v.w;
    }
#pragma unroll
    for (int o = 16; o > 0; o >>= 1) sum += __shfl_xor_sync(0xffffffffu, sum, o);
    __syncthreads();
    if (lane == 0) wred[w] = sum;
    __syncthreads();
    sum = 0.f;
#pragma unroll
    for (int q = 0; q < 8; q++) sum += wred[q];
    const float inv = 1.0f / sum;

    for (int j = tid; j < nvec; j += 256) {
        float4 v = *(float4*)(buf + j * 4);
        __half2 h0 = __floats2half2_rn(v.x * inv, v.y * inv);
        __half2 h1 = __floats2half2_rn(v.z * inv, v.w * inv);
        uint2 u;
        u.x = *(uint32_t*)&h0;
        u.y = *(uint32_t*)&h1;
        ((uint2*)prow)[j] = u;
    }
    for (int j = nvec + tid; j < NT / 4; j += 256)
        ((uint2*)prow)[j] = make_uint2(0u, 0u);
}

// ============================ launch ============================
extern "C" void kernel_launch(void* const* d_in, const int* in_sizes, int n_in,
                              void* d_out, int out_size)
{
    const float* x  = (const float*)d_in[0];
    const float* Wq = (const float*)d_in[1];
    const float* bq = (const float*)d_in[2];
    const float* Wk = (const float*)d_in[3];
    const float* bk = (const float*)d_in[4];
    const float* Wv = (const float*)d_in[5];
    const float* bv = (const float*)d_in[6];
    float* out = (float*)d_out;

    cudaFuncSetAttribute(projQK_k, cudaFuncAttributeMaxDynamicSharedMemorySize, SMEM_T);
    cudaFuncSetAttribute(projV_k,  cudaFuncAttributeMaxDynamicSharedMemorySize, SMEM_T);
    cudaFuncSetAttribute(score_k,  cudaFuncAttributeMaxDynamicSharedMemorySize, SMEM_T);
    cudaFuncSetAttribute(av_k,     cudaFuncAttributeMaxDynamicSharedMemorySize, SMEM_T);

    // persistent side stream + events (host objects only; same recorded work
    // every call -> deterministic, graph-capturable)
    static cudaStream_t s2 = nullptr;
    static cudaEvent_t eFork = nullptr, eX = nullptr, eW = nullptr, eV = nullptr;
    if (!s2) {
        cudaStreamCreateWithFlags(&s2, cudaStreamNonBlocking);
        cudaEventCreateWithFlags(&eFork, cudaEventDisableTiming);
        cudaEventCreateWithFlags(&eX,    cudaEventDisableTiming);
        cudaEventCreateWithFlags(&eW,    cudaEventDisableTiming);
        cudaEventCreateWithFlags(&eV,    cudaEventDisableTiming);
    }

    // main stream: fork point, then x conversion
    cudaEventRecord(eFork, 0);
    cvt_x_k<<<NT * DI / 4 / 256, 256>>>(x);
    cudaEventRecord(eX, 0);

    // side stream: join capture, W transpose, then V projection (needs X + W)
    cudaStreamWaitEvent(s2, eFork, 0);
    transW_k<<<dim3(32, 32, 3), dim3(32, 8), 0, s2>>>(Wq, Wk, Wv);
    cudaEventRecord(eW, s2);
    cudaStreamWaitEvent(s2, eX, 0);
    projV_k<<<dim3(8, 32), 256, SMEM_T, s2>>>(bv);
    cudaEventRecord(eV, s2);

    // main stream: QK projections (need W^T), score, softmax
    cudaStreamWaitEvent(0, eW, 0);
    projQK_k<<<dim3(8, 32, 2), 256, SMEM_T>>>(bq, bk);
    score_k<<<528, 256, SMEM_T>>>();
    softmax_k<<<NT, 256>>>();

    // join: av needs probs (main) + V^T (side)
    cudaStreamWaitEvent(0, eV, 0);
    av_k<<<dim3(8, 80), 256, SMEM_T>>>(out);
    reduce_k<<<NT - 1024, 256>>>(out);
}